// round 9
// baseline (speedup 1.0000x reference)
#include <cuda_runtime.h>
#include <stdint.h>

#define NROWS 500000
#define TPB   256
#define ROWS_PER_BLOCK 32     // 8 warps * 4 rows
#define SROW_STRIDE 196       // floats; 196 mod 32 = 4 -> rotates banks per row

template<class T> __device__ __forceinline__ T vmax(T a, T b) { return a > b ? a : b; }
template<class T> __device__ __forceinline__ T vmin(T a, T b) { return a < b ? a : b; }

template<class T> __device__ __forceinline__ void ceF(T& a, T& b) {
    T h = vmax(a, b), l = vmin(a, b); a = h; b = l;
}

// in-lane Batcher odd-even mergesort-8, descending (19 CEs, all fixed)
template<class T> __device__ __forceinline__ void sort8(T K[8]) {
    ceF(K[0],K[1]); ceF(K[2],K[3]); ceF(K[4],K[5]); ceF(K[6],K[7]);
    ceF(K[0],K[2]); ceF(K[1],K[3]); ceF(K[4],K[6]); ceF(K[5],K[7]);
    ceF(K[1],K[2]); ceF(K[5],K[6]);
    ceF(K[0],K[4]); ceF(K[1],K[5]); ceF(K[2],K[6]); ceF(K[3],K[7]);
    ceF(K[2],K[4]); ceF(K[3],K[5]);
    ceF(K[1],K[2]); ceF(K[3],K[4]); ceF(K[5],K[6]);
}

// in-lane bitonic merge-8 (bitonic -> sorted desc), 12 CEs fixed
template<class T> __device__ __forceinline__ void bmerge8(T K[8]) {
    ceF(K[0],K[4]); ceF(K[1],K[5]); ceF(K[2],K[6]); ceF(K[3],K[7]);
    ceF(K[0],K[2]); ceF(K[1],K[3]); ceF(K[4],K[6]); ceF(K[5],K[7]);
    ceF(K[0],K[1]); ceF(K[2],K[3]); ceF(K[4],K[5]); ceF(K[6],K[7]);
}

// cross-lane reversed CE, predicated; reads ALL partners before writing
template<class T> __device__ __forceinline__ void crossRevPred(T K[8], int d, bool km, unsigned m) {
    T q[8];
    #pragma unroll
    for (int r = 0; r < 8; r++) q[r] = __shfl_xor_sync(m, K[7 - r], d);
    #pragma unroll
    for (int r = 0; r < 8; r++) K[r] = km ? vmax(K[r], q[r]) : vmin(K[r], q[r]);
}

// cross-lane reversed prune: keep max both sides; optionally capture max of discarded mins
template<class T, bool CAP>
__device__ __forceinline__ void crossRevMax(T K[8], int d, unsigned m, T* mMin) {
    T q[8];
    #pragma unroll
    for (int r = 0; r < 8; r++) q[r] = __shfl_xor_sync(m, K[7 - r], d);
    T run;
    #pragma unroll
    for (int r = 0; r < 8; r++) {
        if (CAP) { T l = vmin(K[r], q[r]); run = (r == 0) ? l : vmax(run, l); }
        K[r] = vmax(K[r], q[r]);
    }
    if (CAP) *mMin = run;
}

template<class T> __device__ __forceinline__ void crossPred(T K[8], int d, bool km, unsigned m) {
    #pragma unroll
    for (int r = 0; r < 8; r++) {
        T q = __shfl_xor_sync(m, K[r], d);
        K[r] = km ? vmax(K[r], q) : vmin(K[r], q);
    }
}

// Top-16-of-64; input: lane s (in 8-lane group) holds elements 8s..8s+7.
template<class T, bool CAP>
__device__ __forceinline__ void top16net(T K[8], bool P1, unsigned m, T* mMin) {
    sort8(K);
    crossRevPred(K, 1, P1, m);  bmerge8(K);
    crossRevMax<T,false>(K, 3, m, (T*)nullptr);
    crossPred(K, 1, P1, m);     bmerge8(K);
    crossRevMax<T,CAP>(K, 5, m, mMin);
    crossPred(K, 1, P1, m);     bmerge8(K);
}

__device__ __forceinline__ unsigned norm_key(float a, float b, float c, unsigned tag) {
    float n = __fadd_rn(__fadd_rn(__fmul_rn(a, a), __fmul_rn(b, b)), __fmul_rn(c, c));
    return (__float_as_uint(n) & 0xFFFFFFC0u) | tag;
}

__global__ __launch_bounds__(TPB, 7)
void vns_kernel(const float* __restrict__ x, float* __restrict__ out) {
    __shared__ __align__(16) float srow[ROWS_PER_BLOCK][SROW_STRIDE];

    const int lane = threadIdx.x & 31;
    const int wrp  = threadIdx.x >> 5;
    const int s    = lane & 7;
    const int g    = lane >> 3;                        // 0..3 row within warp
    const int lrow = wrp * 4 + g;                      // smem row
    const int row  = blockIdx.x * ROWS_PER_BLOCK + lrow;
    const bool P1  = (s & 1) == 0;
    const int  b   = s & 1;
    const int  q   = s >> 1;

    // ---- load 6 x float4, stage into smem, compute keys from registers ----
    const float* __restrict__ xrow = x + (size_t)row * 192;
    const float4* p4 = (const float4*)xrow + 6 * s;
    float* sr = srow[lrow];
    float4* s4 = (float4*)(sr + 24 * s);
    float4 r0 = p4[0], r1 = p4[1], r2 = p4[2], r3 = p4[3], r4 = p4[4], r5 = p4[5];
    s4[0] = r0; s4[1] = r1; s4[2] = r2; s4[3] = r3; s4[4] = r4; s4[5] = r5;

    const unsigned b63 = 63 - 8 * s;
    unsigned K[8];
    K[0] = norm_key(r0.x, r0.y, r0.z, b63    );
    K[1] = norm_key(r0.w, r1.x, r1.y, b63 - 1);
    K[2] = norm_key(r1.z, r1.w, r2.x, b63 - 2);
    K[3] = norm_key(r2.y, r2.z, r2.w, b63 - 3);
    K[4] = norm_key(r3.x, r3.y, r3.z, b63 - 4);
    K[5] = norm_key(r3.w, r4.x, r4.y, b63 - 5);
    K[6] = norm_key(r4.z, r4.w, r5.x, b63 - 6);
    K[7] = norm_key(r5.y, r5.z, r5.w, b63 - 7);
    __syncwarp();                                      // STS visible to group

    unsigned mMin;
    top16net<unsigned, true>(K, P1, 0xffffffffu, &mMin);
    unsigned key16 = vmax(mMin, __shfl_xor_sync(0xffffffffu, mMin, 1)); // 17th largest

    // ---- exactness checks: adjacent trunc-equal over sorted positions 0..16 ----
    bool bad = false;
    #pragma unroll
    for (int r = 0; r < 7; r++) bad |= (((K[r] ^ K[r + 1]) >> 6) == 0);
    unsigned nb = __shfl_xor_sync(0xffffffffu, K[0], 1);
    unsigned bcmp = b ? key16 : nb;
    bad |= (((K[7] ^ bcmp) >> 6) == 0);
    unsigned bal = __ballot_sync(0xffffffffu, bad);
    bool groupBad = ((bal >> (lane & 24)) & 0xFFu) != 0;

    float* __restrict__ orow = out + (size_t)row * 48;
    const int p0 = 8 * b + 2 * q;

    int idx0, idx1;
    if (!groupBad) {
        unsigned t0 = (q & 1) ? K[2] : K[0];
        unsigned t1 = (q & 1) ? K[6] : K[4];
        unsigned Kp0 = (q & 2) ? t1 : t0;
        unsigned u0 = (q & 1) ? K[3] : K[1];
        unsigned u1 = (q & 1) ? K[7] : K[5];
        unsigned Kp1 = (q & 2) ? u1 : u0;
        idx0 = 63 - (int)(Kp0 & 63u);
        idx1 = 63 - (int)(Kp1 & 63u);
    } else {
        // ---- exact fallback (rare, per 8-lane group): 64-bit (norm, idx) keys ----
        const unsigned gm = 0xFFu << (lane & 24);
        const float4* f4 = (const float4*)(sr + 24 * s);
        float4 a0 = f4[0], a1 = f4[1], a2 = f4[2], a3 = f4[3], a4 = f4[4], a5 = f4[5];
        float N[8];
        N[0] = __fadd_rn(__fadd_rn(__fmul_rn(a0.x,a0.x), __fmul_rn(a0.y,a0.y)), __fmul_rn(a0.z,a0.z));
        N[1] = __fadd_rn(__fadd_rn(__fmul_rn(a0.w,a0.w), __fmul_rn(a1.x,a1.x)), __fmul_rn(a1.y,a1.y));
        N[2] = __fadd_rn(__fadd_rn(__fmul_rn(a1.z,a1.z), __fmul_rn(a1.w,a1.w)), __fmul_rn(a2.x,a2.x));
        N[3] = __fadd_rn(__fadd_rn(__fmul_rn(a2.y,a2.y), __fmul_rn(a2.z,a2.z)), __fmul_rn(a2.w,a2.w));
        N[4] = __fadd_rn(__fadd_rn(__fmul_rn(a3.x,a3.x), __fmul_rn(a3.y,a3.y)), __fmul_rn(a3.z,a3.z));
        N[5] = __fadd_rn(__fadd_rn(__fmul_rn(a3.w,a3.w), __fmul_rn(a4.x,a4.x)), __fmul_rn(a4.y,a4.y));
        N[6] = __fadd_rn(__fadd_rn(__fmul_rn(a4.z,a4.z), __fmul_rn(a4.w,a4.w)), __fmul_rn(a5.x,a5.x));
        N[7] = __fadd_rn(__fadd_rn(__fmul_rn(a5.y,a5.y), __fmul_rn(a5.z,a5.z)), __fmul_rn(a5.w,a5.w));
        unsigned long long A[8];
        #pragma unroll
        for (int j = 0; j < 8; j++)
            A[j] = ((unsigned long long)__float_as_uint(N[j]) << 32) | (unsigned long long)(b63 - j);
        top16net<unsigned long long, false>(A, P1, gm, (unsigned long long*)nullptr);
        unsigned long long t0 = (q & 1) ? A[2] : A[0];
        unsigned long long t1 = (q & 1) ? A[6] : A[4];
        unsigned long long Kp0 = (q & 2) ? t1 : t0;
        unsigned long long u0 = (q & 1) ? A[3] : A[1];
        unsigned long long u1 = (q & 1) ? A[7] : A[5];
        unsigned long long Kp1 = (q & 2) ? u1 : u0;
        idx0 = 63 - (int)(Kp0 & 63ull);
        idx1 = 63 - (int)(Kp1 & 63ull);
    }

    // ---- gather from smem (LDS.32, no L2) and store as 3 x STG.64 ----
    const float* v0 = sr + 3 * idx0;
    const float* v1 = sr + 3 * idx1;
    float a = v0[0], bb = v0[1], c = v0[2];
    float d = v1[0], e  = v1[1], f = v1[2];
    float2* o2 = (float2*)(orow + 3 * p0);             // 24B-aligned (p0 even)
    o2[0] = make_float2(a, bb);
    o2[1] = make_float2(c, d);
    o2[2] = make_float2(e, f);
}

extern "C" void kernel_launch(void* const* d_in, const int* in_sizes, int n_in,
                              void* d_out, int out_size) {
    const float* x = (const float*)d_in[0];
    float* out = (float*)d_out;
    vns_kernel<<<NROWS / ROWS_PER_BLOCK, TPB>>>(x, out);
}

// round 10
// speedup vs baseline: 1.4422x; 1.4422x over previous
#include <cuda_runtime.h>
#include <stdint.h>

#define NROWS 500000
#define TPB   256
#define ROWS_PER_BLOCK 32     // 8 warps * 4 rows

template<class T> __device__ __forceinline__ T vmax(T a, T b) { return a > b ? a : b; }
template<class T> __device__ __forceinline__ T vmin(T a, T b) { return a < b ? a : b; }

template<class T> __device__ __forceinline__ void ceF(T& a, T& b) {
    T h = vmax(a, b), l = vmin(a, b); a = h; b = l;
}

// in-lane Batcher odd-even mergesort-8, descending (19 CEs, all fixed)
template<class T> __device__ __forceinline__ void sort8(T K[8]) {
    ceF(K[0],K[1]); ceF(K[2],K[3]); ceF(K[4],K[5]); ceF(K[6],K[7]);
    ceF(K[0],K[2]); ceF(K[1],K[3]); ceF(K[4],K[6]); ceF(K[5],K[7]);
    ceF(K[1],K[2]); ceF(K[5],K[6]);
    ceF(K[0],K[4]); ceF(K[1],K[5]); ceF(K[2],K[6]); ceF(K[3],K[7]);
    ceF(K[2],K[4]); ceF(K[3],K[5]);
    ceF(K[1],K[2]); ceF(K[3],K[4]); ceF(K[5],K[6]);
}

// in-lane bitonic merge-8 (bitonic -> sorted desc), 12 CEs fixed
template<class T> __device__ __forceinline__ void bmerge8(T K[8]) {
    ceF(K[0],K[4]); ceF(K[1],K[5]); ceF(K[2],K[6]); ceF(K[3],K[7]);
    ceF(K[0],K[2]); ceF(K[1],K[3]); ceF(K[4],K[6]); ceF(K[5],K[7]);
    ceF(K[0],K[1]); ceF(K[2],K[3]); ceF(K[4],K[5]); ceF(K[6],K[7]);
}

// cross-lane reversed CE, predicated; reads ALL partners before writing
template<class T> __device__ __forceinline__ void crossRevPred(T K[8], int d, bool km, unsigned m) {
    T q[8];
    #pragma unroll
    for (int r = 0; r < 8; r++) q[r] = __shfl_xor_sync(m, K[7 - r], d);
    #pragma unroll
    for (int r = 0; r < 8; r++) K[r] = km ? vmax(K[r], q[r]) : vmin(K[r], q[r]);
}

// cross-lane reversed prune: keep max both sides; optionally capture max of discarded mins
template<class T, bool CAP>
__device__ __forceinline__ void crossRevMax(T K[8], int d, unsigned m, T* mMin) {
    T q[8];
    #pragma unroll
    for (int r = 0; r < 8; r++) q[r] = __shfl_xor_sync(m, K[7 - r], d);
    T run;
    #pragma unroll
    for (int r = 0; r < 8; r++) {
        if (CAP) { T l = vmin(K[r], q[r]); run = (r == 0) ? l : vmax(run, l); }
        K[r] = vmax(K[r], q[r]);
    }
    if (CAP) *mMin = run;
}

template<class T> __device__ __forceinline__ void crossPred(T K[8], int d, bool km, unsigned m) {
    #pragma unroll
    for (int r = 0; r < 8; r++) {
        T q = __shfl_xor_sync(m, K[r], d);
        K[r] = km ? vmax(K[r], q) : vmin(K[r], q);
    }
}

// Top-16-of-64; input: lane s (in 8-lane group) holds elements 8s..8s+7.
// Output: lane b=s&1 of each pair holds sorted positions 8b..8b+7.
template<class T, bool CAP>
__device__ __forceinline__ void top16net(T K[8], bool P1, unsigned m, T* mMin) {
    sort8(K);
    crossRevPred(K, 1, P1, m);  bmerge8(K);
    crossRevMax<T,false>(K, 3, m, (T*)nullptr);
    crossPred(K, 1, P1, m);     bmerge8(K);
    crossRevMax<T,CAP>(K, 5, m, mMin);
    crossPred(K, 1, P1, m);     bmerge8(K);
}

__device__ __forceinline__ unsigned norm_key(float a, float b, float c, unsigned tag) {
    float n = __fadd_rn(__fadd_rn(__fmul_rn(a, a), __fmul_rn(b, b)), __fmul_rn(c, c));
    return (__float_as_uint(n) & 0xFFFFFFC0u) | tag;
}

__global__ __launch_bounds__(TPB, 8)
void vns_kernel(const float* __restrict__ x, float* __restrict__ out) {
    const int lane = threadIdx.x & 31;
    const int s    = lane & 7;                         // sublane within row group
    const int row  = blockIdx.x * ROWS_PER_BLOCK + (threadIdx.x >> 5) * 4 + (lane >> 3);
    const bool P1  = (s & 1) == 0;
    const int  b   = s & 1;
    const int  q   = s >> 1;                           // 0..3

    // ---- load 6 x float4; compute keys; let load regs DIE (no F array) ----
    const float* __restrict__ xrow = x + (size_t)row * 192;
    const float4* p4 = (const float4*)xrow + 6 * s;
    const unsigned b63 = 63 - 8 * s;
    unsigned K[8];
    {
        float4 r0 = p4[0], r1 = p4[1], r2 = p4[2], r3 = p4[3], r4 = p4[4], r5 = p4[5];
        K[0] = norm_key(r0.x, r0.y, r0.z, b63    );
        K[1] = norm_key(r0.w, r1.x, r1.y, b63 - 1);
        K[2] = norm_key(r1.z, r1.w, r2.x, b63 - 2);
        K[3] = norm_key(r2.y, r2.z, r2.w, b63 - 3);
        K[4] = norm_key(r3.x, r3.y, r3.z, b63 - 4);
        K[5] = norm_key(r3.w, r4.x, r4.y, b63 - 5);
        K[6] = norm_key(r4.z, r4.w, r5.x, b63 - 6);
        K[7] = norm_key(r5.y, r5.z, r5.w, b63 - 7);
    }

    unsigned mMin;
    top16net<unsigned, true>(K, P1, 0xffffffffu, &mMin);
    unsigned key16 = vmax(mMin, __shfl_xor_sync(0xffffffffu, mMin, 1)); // 17th largest

    // ---- exactness checks: adjacent trunc-equal over sorted positions 0..16 ----
    bool bad = false;
    #pragma unroll
    for (int r = 0; r < 7; r++) bad |= (((K[r] ^ K[r + 1]) >> 6) == 0);
    unsigned nb = __shfl_xor_sync(0xffffffffu, K[0], 1);
    unsigned bcmp = b ? key16 : nb;
    bad |= (((K[7] ^ bcmp) >> 6) == 0);
    unsigned bal = __ballot_sync(0xffffffffu, bad);
    bool groupBad = ((bal >> (lane & 24)) & 0xFFu) != 0;

    int idx0, idx1;
    if (!groupBad) {
        unsigned t0 = (q & 1) ? K[2] : K[0];
        unsigned t1 = (q & 1) ? K[6] : K[4];
        unsigned Kp0 = (q & 2) ? t1 : t0;
        unsigned u0 = (q & 1) ? K[3] : K[1];
        unsigned u1 = (q & 1) ? K[7] : K[5];
        unsigned Kp1 = (q & 2) ? u1 : u0;
        idx0 = 63 - (int)(Kp0 & 63u);
        idx1 = 63 - (int)(Kp1 & 63u);
    } else {
        // ---- exact fallback (rare, ~1e-3 of rows): re-read row, 64-bit keys ----
        const unsigned gm = 0xFFu << (lane & 24);
        float4 r0 = p4[0], r1 = p4[1], r2 = p4[2], r3 = p4[3], r4 = p4[4], r5 = p4[5];
        float N[8];
        N[0] = __fadd_rn(__fadd_rn(__fmul_rn(r0.x,r0.x), __fmul_rn(r0.y,r0.y)), __fmul_rn(r0.z,r0.z));
        N[1] = __fadd_rn(__fadd_rn(__fmul_rn(r0.w,r0.w), __fmul_rn(r1.x,r1.x)), __fmul_rn(r1.y,r1.y));
        N[2] = __fadd_rn(__fadd_rn(__fmul_rn(r1.z,r1.z), __fmul_rn(r1.w,r1.w)), __fmul_rn(r2.x,r2.x));
        N[3] = __fadd_rn(__fadd_rn(__fmul_rn(r2.y,r2.y), __fmul_rn(r2.z,r2.z)), __fmul_rn(r2.w,r2.w));
        N[4] = __fadd_rn(__fadd_rn(__fmul_rn(r3.x,r3.x), __fmul_rn(r3.y,r3.y)), __fmul_rn(r3.z,r3.z));
        N[5] = __fadd_rn(__fadd_rn(__fmul_rn(r3.w,r3.w), __fmul_rn(r4.x,r4.x)), __fmul_rn(r4.y,r4.y));
        N[6] = __fadd_rn(__fadd_rn(__fmul_rn(r4.z,r4.z), __fmul_rn(r4.w,r4.w)), __fmul_rn(r5.x,r5.x));
        N[7] = __fadd_rn(__fadd_rn(__fmul_rn(r5.y,r5.y), __fmul_rn(r5.z,r5.z)), __fmul_rn(r5.w,r5.w));
        unsigned long long A[8];
        #pragma unroll
        for (int j = 0; j < 8; j++)
            A[j] = ((unsigned long long)__float_as_uint(N[j]) << 32) | (unsigned long long)(b63 - j);
        top16net<unsigned long long, false>(A, P1, gm, (unsigned long long*)nullptr);
        unsigned long long t0 = (q & 1) ? A[2] : A[0];
        unsigned long long t1 = (q & 1) ? A[6] : A[4];
        unsigned long long Kp0 = (q & 2) ? t1 : t0;
        unsigned long long u0 = (q & 1) ? A[3] : A[1];
        unsigned long long u1 = (q & 1) ? A[7] : A[5];
        unsigned long long Kp1 = (q & 2) ? u1 : u0;
        idx0 = 63 - (int)(Kp0 & 63ull);
        idx1 = 63 - (int)(Kp1 & 63ull);
    }

    // ---- gather from global (L1-resident: this warp just read these lines) ----
    const float* v0 = xrow + 3 * idx0;
    const float* v1 = xrow + 3 * idx1;
    float a = v0[0], bb = v0[1], c = v0[2];
    float d = v1[0], e  = v1[1], f = v1[2];

    // ---- store positions p0, p0+1 as 3 x STG.64 (8B-aligned: p0 even) ----
    const int p0 = 8 * b + 2 * q;
    float2* o2 = (float2*)(out + (size_t)row * 48 + 3 * p0);
    o2[0] = make_float2(a, bb);
    o2[1] = make_float2(c, d);
    o2[2] = make_float2(e, f);
}

extern "C" void kernel_launch(void* const* d_in, const int* in_sizes, int n_in,
                              void* d_out, int out_size) {
    const float* x = (const float*)d_in[0];
    float* out = (float*)d_out;
    vns_kernel<<<NROWS / ROWS_PER_BLOCK, TPB>>>(x, out);
}

// round 11
// speedup vs baseline: 1.4769x; 1.0240x over previous
#include <cuda_runtime.h>
#include <stdint.h>

#define NROWS 500000
#define TPB   256
#define ROWS_PER_BLOCK 32     // 8 warps * 4 rows

template<class T> __device__ __forceinline__ T vmax(T a, T b) { return a > b ? a : b; }
template<class T> __device__ __forceinline__ T vmin(T a, T b) { return a < b ? a : b; }

template<class T> __device__ __forceinline__ void ceF(T& a, T& b) {
    T h = vmax(a, b), l = vmin(a, b); a = h; b = l;
}

// in-lane Batcher odd-even mergesort-8, descending (19 CEs, all fixed)
template<class T> __device__ __forceinline__ void sort8(T K[8]) {
    ceF(K[0],K[1]); ceF(K[2],K[3]); ceF(K[4],K[5]); ceF(K[6],K[7]);
    ceF(K[0],K[2]); ceF(K[1],K[3]); ceF(K[4],K[6]); ceF(K[5],K[7]);
    ceF(K[1],K[2]); ceF(K[5],K[6]);
    ceF(K[0],K[4]); ceF(K[1],K[5]); ceF(K[2],K[6]); ceF(K[3],K[7]);
    ceF(K[2],K[4]); ceF(K[3],K[5]);
    ceF(K[1],K[2]); ceF(K[3],K[4]); ceF(K[5],K[6]);
}

// in-lane bitonic merge-8 (bitonic -> sorted desc), 12 CEs fixed
template<class T> __device__ __forceinline__ void bmerge8(T K[8]) {
    ceF(K[0],K[4]); ceF(K[1],K[5]); ceF(K[2],K[6]); ceF(K[3],K[7]);
    ceF(K[0],K[2]); ceF(K[1],K[3]); ceF(K[4],K[6]); ceF(K[5],K[7]);
    ceF(K[0],K[1]); ceF(K[2],K[3]); ceF(K[4],K[5]); ceF(K[6],K[7]);
}

// cross-lane reversed CE, predicated; reads ALL partners before writing
template<class T> __device__ __forceinline__ void crossRevPred(T K[8], int d, bool km, unsigned m) {
    T q[8];
    #pragma unroll
    for (int r = 0; r < 8; r++) q[r] = __shfl_xor_sync(m, K[7 - r], d);
    #pragma unroll
    for (int r = 0; r < 8; r++) K[r] = km ? vmax(K[r], q[r]) : vmin(K[r], q[r]);
}

// cross-lane reversed prune: keep max both sides; optionally capture max of discarded mins
template<class T, bool CAP>
__device__ __forceinline__ void crossRevMax(T K[8], int d, unsigned m, T* mMin) {
    T q[8];
    #pragma unroll
    for (int r = 0; r < 8; r++) q[r] = __shfl_xor_sync(m, K[7 - r], d);
    T run;
    #pragma unroll
    for (int r = 0; r < 8; r++) {
        if (CAP) { T l = vmin(K[r], q[r]); run = (r == 0) ? l : vmax(run, l); }
        K[r] = vmax(K[r], q[r]);
    }
    if (CAP) *mMin = run;
}

template<class T> __device__ __forceinline__ void crossPred(T K[8], int d, bool km, unsigned m) {
    #pragma unroll
    for (int r = 0; r < 8; r++) {
        T q = __shfl_xor_sync(m, K[r], d);
        K[r] = km ? vmax(K[r], q) : vmin(K[r], q);
    }
}

// Top-16-of-64; input: lane s (in 8-lane group) holds elements 8s..8s+7.
// Output: lane b=s&1 of each pair holds sorted positions 8b..8b+7.
template<class T, bool CAP>
__device__ __forceinline__ void top16net(T K[8], bool P1, unsigned m, T* mMin) {
    sort8(K);
    crossRevPred(K, 1, P1, m);  bmerge8(K);
    crossRevMax<T,false>(K, 3, m, (T*)nullptr);
    crossPred(K, 1, P1, m);     bmerge8(K);
    crossRevMax<T,CAP>(K, 5, m, mMin);
    crossPred(K, 1, P1, m);     bmerge8(K);
}

__device__ __forceinline__ unsigned norm_key(float a, float b, float c, unsigned tag) {
    float n = __fadd_rn(__fadd_rn(__fmul_rn(a, a), __fmul_rn(b, b)), __fmul_rn(c, c));
    return (__float_as_uint(n) & 0xFFFFFFC0u) | tag;
}

// gather one 3-float vector with 1 LDG.64 + 1 LDG.32 (8B-aligned split by parity)
__device__ __forceinline__ void gather_vec(const float* __restrict__ xrow, int idx,
                                           float& a, float& b, float& c) {
    bool odd = (idx & 1);
    int e = 3 * idx + (odd ? 1 : 0);       // even float offset -> 8B aligned
    int o = odd ? 3 * idx : 3 * idx + 2;   // the single float
    float2 f2 = *(const float2*)(xrow + e);
    float  f1 = xrow[o];
    a = odd ? f1   : f2.x;
    b = odd ? f2.x : f2.y;
    c = odd ? f2.y : f1;
}

__global__ __launch_bounds__(TPB, 8)
void vns_kernel(const float* __restrict__ x, float* __restrict__ out) {
    const int lane = threadIdx.x & 31;
    const int s    = lane & 7;                         // sublane within row group
    const int row  = blockIdx.x * ROWS_PER_BLOCK + (threadIdx.x >> 5) * 4 + (lane >> 3);
    const bool P1  = (s & 1) == 0;
    const int  b   = s & 1;
    const int  q   = s >> 1;                           // 0..3

    // ---- load 6 x float4; compute keys; let load regs DIE ----
    const float* __restrict__ xrow = x + (size_t)row * 192;
    const float4* p4 = (const float4*)xrow + 6 * s;
    const unsigned b63 = 63 - 8 * s;
    unsigned K[8];
    {
        float4 r0 = p4[0], r1 = p4[1], r2 = p4[2], r3 = p4[3], r4 = p4[4], r5 = p4[5];
        K[0] = norm_key(r0.x, r0.y, r0.z, b63    );
        K[1] = norm_key(r0.w, r1.x, r1.y, b63 - 1);
        K[2] = norm_key(r1.z, r1.w, r2.x, b63 - 2);
        K[3] = norm_key(r2.y, r2.z, r2.w, b63 - 3);
        K[4] = norm_key(r3.x, r3.y, r3.z, b63 - 4);
        K[5] = norm_key(r3.w, r4.x, r4.y, b63 - 5);
        K[6] = norm_key(r4.z, r4.w, r5.x, b63 - 6);
        K[7] = norm_key(r5.y, r5.z, r5.w, b63 - 7);
    }

    unsigned mMin;
    top16net<unsigned, true>(K, P1, 0xffffffffu, &mMin);
    unsigned key16 = vmax(mMin, __shfl_xor_sync(0xffffffffu, mMin, 1)); // 17th largest

    // ---- exactness checks: adjacent trunc-equal over sorted positions 0..16 ----
    bool bad = false;
    #pragma unroll
    for (int r = 0; r < 7; r++) bad |= (((K[r] ^ K[r + 1]) >> 6) == 0);
    unsigned nb = __shfl_xor_sync(0xffffffffu, K[0], 1);
    unsigned bcmp = b ? key16 : nb;
    bad |= (((K[7] ^ bcmp) >> 6) == 0);
    unsigned bal = __ballot_sync(0xffffffffu, bad);
    bool groupBad = ((bal >> (lane & 24)) & 0xFFu) != 0;

    int idx0, idx1;
    if (!groupBad) {
        unsigned t0 = (q & 1) ? K[2] : K[0];
        unsigned t1 = (q & 1) ? K[6] : K[4];
        unsigned Kp0 = (q & 2) ? t1 : t0;
        unsigned u0 = (q & 1) ? K[3] : K[1];
        unsigned u1 = (q & 1) ? K[7] : K[5];
        unsigned Kp1 = (q & 2) ? u1 : u0;
        idx0 = 63 - (int)(Kp0 & 63u);
        idx1 = 63 - (int)(Kp1 & 63u);
    } else {
        // ---- exact fallback (rare, ~1e-3 of rows): re-read row, 64-bit keys ----
        const unsigned gm = 0xFFu << (lane & 24);
        float4 r0 = p4[0], r1 = p4[1], r2 = p4[2], r3 = p4[3], r4 = p4[4], r5 = p4[5];
        float N[8];
        N[0] = __fadd_rn(__fadd_rn(__fmul_rn(r0.x,r0.x), __fmul_rn(r0.y,r0.y)), __fmul_rn(r0.z,r0.z));
        N[1] = __fadd_rn(__fadd_rn(__fmul_rn(r0.w,r0.w), __fmul_rn(r1.x,r1.x)), __fmul_rn(r1.y,r1.y));
        N[2] = __fadd_rn(__fadd_rn(__fmul_rn(r1.z,r1.z), __fmul_rn(r1.w,r1.w)), __fmul_rn(r2.x,r2.x));
        N[3] = __fadd_rn(__fadd_rn(__fmul_rn(r2.y,r2.y), __fmul_rn(r2.z,r2.z)), __fmul_rn(r2.w,r2.w));
        N[4] = __fadd_rn(__fadd_rn(__fmul_rn(r3.x,r3.x), __fmul_rn(r3.y,r3.y)), __fmul_rn(r3.z,r3.z));
        N[5] = __fadd_rn(__fadd_rn(__fmul_rn(r3.w,r3.w), __fmul_rn(r4.x,r4.x)), __fmul_rn(r4.y,r4.y));
        N[6] = __fadd_rn(__fadd_rn(__fmul_rn(r4.z,r4.z), __fmul_rn(r4.w,r4.w)), __fmul_rn(r5.x,r5.x));
        N[7] = __fadd_rn(__fadd_rn(__fmul_rn(r5.y,r5.y), __fmul_rn(r5.z,r5.z)), __fmul_rn(r5.w,r5.w));
        unsigned long long A[8];
        #pragma unroll
        for (int j = 0; j < 8; j++)
            A[j] = ((unsigned long long)__float_as_uint(N[j]) << 32) | (unsigned long long)(b63 - j);
        top16net<unsigned long long, false>(A, P1, gm, (unsigned long long*)nullptr);
        unsigned long long t0 = (q & 1) ? A[2] : A[0];
        unsigned long long t1 = (q & 1) ? A[6] : A[4];
        unsigned long long Kp0 = (q & 2) ? t1 : t0;
        unsigned long long u0 = (q & 1) ? A[3] : A[1];
        unsigned long long u1 = (q & 1) ? A[7] : A[5];
        unsigned long long Kp1 = (q & 2) ? u1 : u0;
        idx0 = 63 - (int)(Kp0 & 63ull);
        idx1 = 63 - (int)(Kp1 & 63ull);
    }

    // ---- gather: 2 instrs per vector (LDG.64 + LDG.32), L1-resident lines ----
    float a, bb, c, d, e, f;
    gather_vec(xrow, idx0, a, bb, c);
    gather_vec(xrow, idx1, d, e, f);

    // ---- store positions p0, p0+1 as 3 x STG.64 (8B-aligned: p0 even) ----
    const int p0 = 8 * b + 2 * q;
    float2* o2 = (float2*)(out + (size_t)row * 48 + 3 * p0);
    o2[0] = make_float2(a, bb);
    o2[1] = make_float2(c, d);
    o2[2] = make_float2(e, f);
}

extern "C" void kernel_launch(void* const* d_in, const int* in_sizes, int n_in,
                              void* d_out, int out_size) {
    const float* x = (const float*)d_in[0];
    float* out = (float*)d_out;
    vns_kernel<<<NROWS / ROWS_PER_BLOCK, TPB>>>(x, out);
}